// round 15
// baseline (speedup 1.0000x reference)
#include <cuda_runtime.h>
#include <cuda_bf16.h>
#include <cstdint>
#include <math.h>

// Problem constants
constexpr int Bc  = 32;
constexpr int Nc  = 512;
constexpr int INc = 128;
constexpr int Dc  = 256;
constexpr int Hc  = 8;
constexpr int Lc  = 2;
constexpr int Rc  = 10;
constexpr int FFc = 2048;
constexpr int Vc  = 10;
constexpr int Mc  = Bc * Nc;        // 16384
constexpr int MPAD = Mc + 256;      // 16640 = 260*64
constexpr int QS  = 3 * Dc;         // 768

// -------- scratch (device globals) ----------
__device__ float g_qkv[Mc * QS];    // reused as 2x bf16 (hi|lo) qkv
__device__ float g_t[Mc * Dc];
__device__ float g_bt[Lc * 2 * QS];
__device__ int   g_perm[MPAD];
__device__ int   g_meta[4];
// bf16 hi/lo activation splits
__device__ __nv_bfloat16 g_xs[2][Mc * INc];
__device__ __nv_bfloat16 g_hsA[2][Mc * Dc];
__device__ __nv_bfloat16 g_hsB[2][Mc * Dc];
__device__ __nv_bfloat16 g_msgs[2][Mc * Dc];
__device__ __nv_bfloat16 g_ffs[2][(size_t)Mc * FFc];
__device__ __nv_bfloat16 g_lns[2][Mc * Dc];
// bf16 hi/lo transposed weights [N][K]
__device__ __nv_bfloat16 g_binT[2][Dc * INc];
__device__ __nv_bfloat16 g_qkvT[Lc][2][2][QS * Dc];   // [layer][type][hi/lo]
__device__ __nv_bfloat16 g_woT[Lc][2][2][Dc * Dc];
__device__ __nv_bfloat16 g_encT[2][QS * Dc];
__device__ __nv_bfloat16 g_wotT[2][Dc * Dc];
__device__ __nv_bfloat16 g_f1T[2][FFc * Dc];
__device__ __nv_bfloat16 g_f2T[2][Dc * FFc];

// ---------------------------------------------------------------------------
// helpers
// ---------------------------------------------------------------------------
__device__ __forceinline__ uint32_t smem_u32(const void* p) {
    uint32_t a;
    asm("{ .reg .u64 t; cvta.to.shared.u64 t, %1; cvt.u32.u64 %0, t; }"
        : "=r"(a) : "l"(p));
    return a;
}
#define SWZ128(o) ((o) ^ (((o) >> 3) & 0x70))

#define CP_A16(sm, gm) \
    asm volatile("cp.async.cg.shared.global [%0], [%1], 16;" :: "r"(sm), "l"(gm))
#define CP_COMMIT() asm volatile("cp.async.commit_group;" ::: "memory")
#define CP_WAIT1()  asm volatile("cp.async.wait_group 1;" ::: "memory")
#define CP_WAIT0()  asm volatile("cp.async.wait_group 0;" ::: "memory")

#define LDSM4(r, addr) \
    asm volatile("ldmatrix.sync.aligned.m8n8.x4.shared.b16 {%0,%1,%2,%3}, [%4];" \
        : "=r"((r)[0]), "=r"((r)[1]), "=r"((r)[2]), "=r"((r)[3]) : "r"(addr))
#define LDSM4T(r, addr) \
    asm volatile("ldmatrix.sync.aligned.m8n8.x4.trans.shared.b16 {%0,%1,%2,%3}, [%4];" \
        : "=r"((r)[0]), "=r"((r)[1]), "=r"((r)[2]), "=r"((r)[3]) : "r"(addr))

#define MMA16816(d, a, b0_, b1_) \
    asm volatile("mma.sync.aligned.m16n8k16.row.col.f32.bf16.bf16.f32 " \
        "{%0,%1,%2,%3}, {%4,%5,%6,%7}, {%8,%9}, {%0,%1,%2,%3};" \
        : "+f"((d)[0]), "+f"((d)[1]), "+f"((d)[2]), "+f"((d)[3]) \
        : "r"((a)[0]), "r"((a)[1]), "r"((a)[2]), "r"((a)[3]), "r"(b0_), "r"(b1_))

__device__ __forceinline__ void split_bf(float v, __nv_bfloat16& h, __nv_bfloat16& l) {
    h = __float2bfloat16(v);
    l = __float2bfloat16(v - __bfloat162float(h));
}
__device__ __forceinline__ uint32_t pack2(float lo, float hi) {
    uint32_t d;
    asm("cvt.rn.bf16x2.f32 %0, %1, %2;" : "=r"(d) : "f"(hi), "f"(lo));
    return d;
}
__device__ __forceinline__ float lo_of(float p) {
    return p - __bfloat162float(__float2bfloat16(p));
}

// ---------------------------------------------------------------------------
// setup_perm: partition rows by node type
// ---------------------------------------------------------------------------
__global__ void setup_perm(const int* __restrict__ types,
                           int* __restrict__ perm, int* __restrict__ meta)
{
    __shared__ int s[Nc];
    int n = threadIdx.x;
    int tp = types[n];
    s[n] = (tp == 0) ? 1 : 0;
    __syncthreads();
    for (int off = 1; off < Nc; off <<= 1) {
        int v = s[n];
        int add = (n >= off) ? s[n - off] : 0;
        __syncthreads();
        s[n] = v + add;
        __syncthreads();
    }
    int count0 = s[Nc - 1];
    int rank = (tp == 0) ? (s[n] - 1) : (n - s[n]);
    int rows0  = count0 * Bc;
    int rows0p = (rows0 + 127) & ~127;
    int base = (tp == 0) ? rank * Bc : rows0p + rank * Bc;
    for (int b = 0; b < Bc; b++)
        perm[base + b] = b * Nc + n;
    if (n == 0) meta[0] = rows0p;
    __syncthreads();
    int rows1 = (Nc - count0) * Bc;
    int total = rows0p + rows1;
    for (int i = n; i < MPAD; i += Nc)
        if ((i >= rows0 && i < rows0p) || i >= total) perm[i] = -1;
}

// ---------------------------------------------------------------------------
// prep_all: fused transpose(or copy)+bf16-split for all fp32->bf16 conversions
// ---------------------------------------------------------------------------
constexpr int MAXJOBS = 24;
struct PrepJobs {
    const float* src[MAXJOBS];
    __nv_bfloat16* dhi[MAXJOBS];
    __nv_bfloat16* dlo[MAXJOBS];
    int K[MAXJOBS];
    int N[MAXJOBS];
    int trans[MAXJOBS];
    int tile_off[MAXJOBS + 1];
    int njobs;
};

__global__ __launch_bounds__(256)
void prep_all(PrepJobs J)
{
    __shared__ float tile[32][33];
    int bid = blockIdx.x;
    int j = 0;
#pragma unroll 1
    while (j + 1 < J.njobs && bid >= J.tile_off[j + 1]) j++;
    int local = bid - J.tile_off[j];
    const float* src = J.src[j];
    __nv_bfloat16* dhi = J.dhi[j];
    __nv_bfloat16* dlo = J.dlo[j];
    int K = J.K[j], N = J.N[j];
    int tn = N >> 5;
    int n0 = (local % tn) * 32, k0 = (local / tn) * 32;

    int tx = threadIdx.x & 31, ty = threadIdx.x >> 5;
    if (J.trans[j]) {
#pragma unroll
        for (int i = 0; i < 4; i++)
            tile[ty + 8 * i][tx] = src[(size_t)(k0 + ty + 8 * i) * N + n0 + tx];
        __syncthreads();
#pragma unroll
        for (int i = 0; i < 4; i++) {
            int n = n0 + ty + 8 * i;
            int k = k0 + tx;
            float v = tile[tx][ty + 8 * i];
            __nv_bfloat16 h, l;
            split_bf(v, h, l);
            dhi[(size_t)n * K + k] = h;
            dlo[(size_t)n * K + k] = l;
        }
    } else {
#pragma unroll
        for (int i = 0; i < 4; i++) {
            size_t o = (size_t)(k0 + ty + 8 * i) * N + n0 + tx;
            float v = src[o];
            __nv_bfloat16 h, l;
            split_bf(v, h, l);
            dhi[o] = h;
            dlo[o] = l;
        }
    }
}

// pack typed QKV biases for all layers: out[Lc][2][QS]
__global__ void pack_b2(const float* __restrict__ bq, const float* __restrict__ bk,
                        const float* __restrict__ bv, float* __restrict__ out)
{
    int idx = blockIdx.x * 256 + threadIdx.x;
    if (idx >= Lc * 2 * QS) return;
    int lt = idx / QS, j = idx % QS;
    const float* src = (j < Dc) ? bq : ((j < 2 * Dc) ? bk : bv);
    out[idx] = src[lt * Dc + (j & (Dc - 1))];
}

// ---------------------------------------------------------------------------
// bf16 mma.sync GEMM with FUSED 3-product split (R14 winner) + direct-STG
// epilogue: store straight from accumulators (all stores 32B-sector aligned),
// no smem bounce, no epilogue barriers.
// Tile 64x128, warp tile 32x32, 2-stage cp.async, 2 CTAs/SM.
// ---------------------------------------------------------------------------
constexpr int MM_A_HI = 0;
constexpr int MM_A_LO = 8192;
constexpr int MM_B_HI = 16384;
constexpr int MM_B_LO = 32768;
constexpr int MM_STAGE = 49152;       // Ahi 8K + Alo 8K + Bhi 16K + Blo 16K
constexpr int MMB_DYN = 2 * MM_STAGE; // 98304

__global__ __launch_bounds__(256, 2)
void mm_bf(const __nv_bfloat16* __restrict__ Ahi, const __nv_bfloat16* __restrict__ Alo,
           int K, int N,
           const __nv_bfloat16* __restrict__ Bhi0, const __nv_bfloat16* __restrict__ Blo0,
           const __nv_bfloat16* __restrict__ Bhi1, const __nv_bfloat16* __restrict__ Blo1,
           const float* __restrict__ bias0, const float* __restrict__ bias1,
           const int* __restrict__ perm, const int* __restrict__ meta,
           const __nv_bfloat16* __restrict__ resH, const __nv_bfloat16* __restrict__ resL,
           float* __restrict__ Cf,
           __nv_bfloat16* __restrict__ Chi, __nv_bfloat16* __restrict__ Clo,
           int do_relu)
{
    extern __shared__ char sb[];
    __shared__ int sPerm[64];

    const int t = threadIdx.x;
    const int m0 = blockIdx.y * 64, n0 = blockIdx.x * 128;
    const bool typed = (perm != nullptr);

    const __nv_bfloat16* Bhi = Bhi0;
    const __nv_bfloat16* Blo = Blo0;
    const float* bias = bias0;
    if (typed && m0 >= meta[0]) { Bhi = Bhi1; Blo = Blo1; bias = bias1; }

    if (t < 64) sPerm[t] = typed ? perm[m0 + t] : (m0 + t);
    __syncthreads();

    // loader: lr = row lane (0..31), ch = 16B chunk (0..7)
    const int lr = t >> 3, ch = t & 7;
    int ag0 = sPerm[lr];      if (ag0 < 0) ag0 = 0;
    int ag1 = sPerm[lr + 32]; if (ag1 < 0) ag1 = 0;
    const uint32_t aoff0 = (uint32_t)ag0 * K + ch * 8;
    const uint32_t aoff1 = (uint32_t)ag1 * K + ch * 8;
    uint32_t boff[4], offB[4];
#pragma unroll
    for (int j = 0; j < 4; j++) {
        boff[j] = (uint32_t)(n0 + lr + 32 * j) * K + ch * 8;
        offB[j] = SWZ128((uint32_t)((lr + 32 * j) * 128 + ch * 16));
    }
    const uint32_t offA0 = SWZ128((uint32_t)(lr * 128 + ch * 16));
    const uint32_t offA1 = SWZ128((uint32_t)((lr + 32) * 128 + ch * 16));
    const uint32_t sbase = smem_u32(sb);
    const int S = K >> 6;              // K/64 chunks

    auto issue_load = [&](int kc, int stg) {
        int k0 = kc * 64;
        uint32_t so = sbase + stg * MM_STAGE;
        CP_A16(so + MM_A_HI + offA0, Ahi + aoff0 + k0);
        CP_A16(so + MM_A_HI + offA1, Ahi + aoff1 + k0);
        CP_A16(so + MM_A_LO + offA0, Alo + aoff0 + k0);
        CP_A16(so + MM_A_LO + offA1, Alo + aoff1 + k0);
#pragma unroll
        for (int j = 0; j < 4; j++) {
            CP_A16(so + MM_B_HI + offB[j], Bhi + boff[j] + k0);
            CP_A16(so + MM_B_LO + offB[j], Blo + boff[j] + k0);
        }
        CP_COMMIT();
    };

    float acc[2][4][4] = {};
    const int wid = t >> 5, lane = t & 31;
    const int wm = wid & 1, wn = wid >> 1;

    issue_load(0, 0);
    if (S > 1) issue_load(1, 1);

    for (int kc = 0; kc < S; kc++) {
        if (kc + 1 < S) { CP_WAIT1(); } else { CP_WAIT0(); }
        __syncthreads();
        uint32_t stg = sbase + (kc & 1) * MM_STAGE;
#pragma unroll
        for (int kk = 0; kk < 64; kk += 16) {
            uint32_t ah[2][4], al[2][4], bh[2][4], bl[2][4];
#pragma unroll
            for (int mi = 0; mi < 2; mi++) {
                int row = wm * 32 + mi * 16 + (lane & 15);
                int kcol = kk + ((lane >> 4) << 3);
                uint32_t off = SWZ128((uint32_t)(row * 128 + kcol * 2));
                LDSM4(ah[mi], stg + MM_A_HI + off);
                LDSM4(al[mi], stg + MM_A_LO + off);
            }
#pragma unroll
            for (int bj = 0; bj < 2; bj++) {
                int nrow = wn * 32 + bj * 16 + ((lane >> 4) & 1) * 8 + (lane & 7);
                int kcol = kk + ((lane >> 3) & 1) * 8;
                uint32_t off = SWZ128((uint32_t)(nrow * 128 + kcol * 2));
                LDSM4(bh[bj], stg + MM_B_HI + off);
                LDSM4(bl[bj], stg + MM_B_LO + off);
            }
#pragma unroll
            for (int mi = 0; mi < 2; mi++)
#pragma unroll
                for (int bj = 0; bj < 2; bj++) {
                    MMA16816(acc[mi][bj * 2],     ah[mi], bh[bj][0], bh[bj][1]);
                    MMA16816(acc[mi][bj * 2 + 1], ah[mi], bh[bj][2], bh[bj][3]);
                    MMA16816(acc[mi][bj * 2],     al[mi], bh[bj][0], bh[bj][1]);
                    MMA16816(acc[mi][bj * 2 + 1], al[mi], bh[bj][2], bh[bj][3]);
                    MMA16816(acc[mi][bj * 2],     ah[mi], bl[bj][0], bl[bj][1]);
                    MMA16816(acc[mi][bj * 2 + 1], ah[mi], bl[bj][2], bl[bj][3]);
                }
        }
        __syncthreads();
        if (kc + 2 < S) issue_load(kc + 2, kc & 1);
    }

    // ------ direct-STG epilogue: all stores are 32B-sector aligned ------
    // fragment (mi, nj) rows: wm*32 + mi*16 + (lane>>2) + {0, 8}
    //            cols: n0 + wn*32 + nj*8 + (lane&3)*2  (float2 / bf16x2)
    {
        const int rbase = wm * 32 + (lane >> 2);
        const int cbase = n0 + wn * 32 + (lane & 3) * 2;
        float2 bv[4];
#pragma unroll
        for (int nj = 0; nj < 4; nj++)
            bv[nj] = *reinterpret_cast<const float2*>(&bias[cbase + nj * 8]);

#pragma unroll
        for (int mi = 0; mi < 2; mi++)
#pragma unroll
            for (int rr = 0; rr < 2; rr++) {
                int r = rbase + mi * 16 + rr * 8;
                int g = sPerm[r];
                if (g < 0) continue;
#pragma unroll
                for (int nj = 0; nj < 4; nj++) {
                    float2 v;
                    v.x = acc[mi][nj][rr * 2 + 0] + bv[nj].x;
                    v.y = acc[mi][nj][rr * 2 + 1] + bv[nj].y;
                    if (do_relu) { v.x = fmaxf(v.x, 0.f); v.y = fmaxf(v.y, 0.f); }
                    size_t o = (size_t)g * N + cbase + nj * 8;
                    if (resH) {
                        __nv_bfloat162 rh = *reinterpret_cast<const __nv_bfloat162*>(resH + o);
                        __nv_bfloat162 rl = *reinterpret_cast<const __nv_bfloat162*>(resL + o);
                        v.x += __bfloat162float(rh.x) + __bfloat162float(rl.x);
                        v.y += __bfloat162float(rh.y) + __bfloat162float(rl.y);
                    }
                    if (Cf) {
                        *reinterpret_cast<float2*>(Cf + o) = v;
                    }
                    if (Chi) {
                        __nv_bfloat16 h0, l0, h1, l1;
                        split_bf(v.x, h0, l0); split_bf(v.y, h1, l1);
                        __nv_bfloat162 ph; ph.x = h0; ph.y = h1;
                        __nv_bfloat162 pl; pl.x = l0; pl.y = l1;
                        *reinterpret_cast<__nv_bfloat162*>(Chi + o) = ph;
                        *reinterpret_cast<__nv_bfloat162*>(Clo + o) = pl;
                    }
                }
            }
    }
}

// ---------------------------------------------------------------------------
// attn3: flash attention on tensor cores (R10 configuration: 3 KV bufs,
// launch_bounds(256,2), 84KB smem).
// ---------------------------------------------------------------------------
constexpr int FA_PITCH = 80;
constexpr int FA_Q_H = 0;
constexpr int FA_Q_L = 10240;
constexpr int FA_KV  = 20480;            // + buf*20480 (3 bufs)
constexpr int FA_KH = 0, FA_KL = 5120, FA_VH = 10240, FA_VL = 15360;
constexpr int FA_BIAS = FA_KV + 3 * 20480;   // 81920
constexpr int FA_SMEM = FA_BIAS + Nc * 4;    // 83968

__global__ __launch_bounds__(256, 2)
void attn3(const __nv_bfloat16* __restrict__ qh, const __nv_bfloat16* __restrict__ ql,
           __nv_bfloat16* __restrict__ outh, __nv_bfloat16* __restrict__ outl,
           const float* __restrict__ relp, const int* __restrict__ rel_ids,
           int do_gelu)
{
    extern __shared__ char sm[];
    const uint32_t sb = smem_u32(sm);
    const int t = threadIdx.x, lane = t & 31, w = t >> 5;
    const int h = blockIdx.y, b = blockIdx.z;
    const int rowbase = b * Nc;
    const int q0 = blockIdx.x * 128;

    float* sBias = (float*)(sm + FA_BIAS);
    for (int i = t; i < Nc; i += 256)
        sBias[i] = relp ? relp[rel_ids[rowbase + i] * Hc + h] : 0.f;

#pragma unroll
    for (int i = 0; i < 2; i++) {
        int id = t + 256 * i;
        int r = id >> 2, ch = id & 3;
        size_t go = (size_t)(rowbase + q0 + r) * QS + h * 32 + ch * 8;
        CP_A16(sb + FA_Q_H + r * FA_PITCH + ch * 16, qh + go);
        CP_A16(sb + FA_Q_L + r * FA_PITCH + ch * 16, ql + go);
    }
    CP_COMMIT();

    auto load_kv = [&](int c, int buf) {
        uint32_t base = sb + FA_KV + buf * 20480;
        int kr0 = rowbase + c * 64;
        int r = t >> 2, ch = t & 3;
#pragma unroll
        for (int m = 0; m < 4; m++) {
            const __nv_bfloat16* src = (m & 1) ? ql : qh;
            int coloff = ((m >> 1) ? 2 * Dc : Dc) + h * 32;
            uint32_t dst = base + ((m >> 1) ? ((m & 1) ? FA_VL : FA_VH)
                                            : ((m & 1) ? FA_KL : FA_KH));
            CP_A16(dst + r * FA_PITCH + ch * 16,
                   src + (size_t)(kr0 + r) * QS + coloff + ch * 8);
        }
        CP_COMMIT();
    };

    uint32_t qfh[2][4], qfl[2][4];
    float m_[2] = {-1e30f, -1e30f};
    float l_[2] = {0.f, 0.f};
    float oc[4][4] = {};

    load_kv(0, 0);
    load_kv(1, 1);

    constexpr int NCH = Nc / 64;   // 8
    int cur = 0, nxt2 = 2;
    for (int c = 0; c < NCH; c++) {
        if (c + 1 < NCH) { CP_WAIT1(); } else { CP_WAIT0(); }
        __syncthreads();
        if (c + 2 < NCH) load_kv(c + 2, nxt2);
        if (c == 0) {
#pragma unroll
            for (int ks = 0; ks < 2; ks++) {
                uint32_t off = (uint32_t)(w * 16 + (lane & 15)) * FA_PITCH
                             + (ks * 16 + (lane >> 4) * 8) * 2;
                LDSM4(qfh[ks], sb + FA_Q_H + off);
                LDSM4(qfl[ks], sb + FA_Q_L + off);
            }
        }
        uint32_t kvb = sb + FA_KV + cur * 20480;

        float S[8][4];
#pragma unroll
        for (int j = 0; j < 8; j++) { S[j][0] = S[j][1] = S[j][2] = S[j][3] = 0.f; }
#pragma unroll
        for (int pj = 0; pj < 4; pj++) {
#pragma unroll
            for (int ks = 0; ks < 2; ks++) {
                uint32_t off = (uint32_t)(pj * 16 + ((lane >> 4) & 1) * 8 + (lane & 7)) * FA_PITCH
                             + (ks * 16 + ((lane >> 3) & 1) * 8) * 2;
                uint32_t kh[4], kl[4];
                LDSM4(kh, kvb + FA_KH + off);
                LDSM4(kl, kvb + FA_KL + off);
                MMA16816(S[2 * pj],     qfh[ks], kh[0], kh[1]);
                MMA16816(S[2 * pj + 1], qfh[ks], kh[2], kh[3]);
                MMA16816(S[2 * pj],     qfl[ks], kh[0], kh[1]);
                MMA16816(S[2 * pj + 1], qfl[ks], kh[2], kh[3]);
                MMA16816(S[2 * pj],     qfh[ks], kl[0], kl[1]);
                MMA16816(S[2 * pj + 1], qfh[ks], kl[2], kl[3]);
            }
        }

        const float scl = 0.17677669529663687f;
        float mc0 = -1e30f, mc1 = -1e30f;
#pragma unroll
        for (int j = 0; j < 8; j++) {
            float b0 = sBias[c * 64 + j * 8 + (lane & 3) * 2];
            float b1 = sBias[c * 64 + j * 8 + (lane & 3) * 2 + 1];
            S[j][0] = fmaf(S[j][0], scl, b0);
            S[j][1] = fmaf(S[j][1], scl, b1);
            S[j][2] = fmaf(S[j][2], scl, b0);
            S[j][3] = fmaf(S[j][3], scl, b1);
            mc0 = fmaxf(mc0, fmaxf(S[j][0], S[j][1]));
            mc1 = fmaxf(mc1, fmaxf(S[j][2], S[j][3]));
        }
#pragma unroll
        for (int o = 1; o <= 2; o <<= 1) {
            mc0 = fmaxf(mc0, __shfl_xor_sync(0xffffffffu, mc0, o));
            mc1 = fmaxf(mc1, __shfl_xor_sync(0xffffffffu, mc1, o));
        }
        float mn0 = fmaxf(m_[0], mc0), mn1 = fmaxf(m_[1], mc1);
        float al0 = __expf(m_[0] - mn0), al1 = __expf(m_[1] - mn1);
        m_[0] = mn0; m_[1] = mn1;
        float ps0 = 0.f, ps1 = 0.f;
#pragma unroll
        for (int j = 0; j < 8; j++) {
            S[j][0] = __expf(S[j][0] - mn0);
            S[j][1] = __expf(S[j][1] - mn0);
            S[j][2] = __expf(S[j][2] - mn1);
            S[j][3] = __expf(S[j][3] - mn1);
            ps0 += S[j][0] + S[j][1];
            ps1 += S[j][2] + S[j][3];
        }
#pragma unroll
        for (int o = 1; o <= 2; o <<= 1) {
            ps0 += __shfl_xor_sync(0xffffffffu, ps0, o);
            ps1 += __shfl_xor_sync(0xffffffffu, ps1, o);
        }
        l_[0] = l_[0] * al0 + ps0;
        l_[1] = l_[1] * al1 + ps1;
#pragma unroll
        for (int j = 0; j < 4; j++) {
            oc[j][0] *= al0; oc[j][1] *= al0;
            oc[j][2] *= al1; oc[j][3] *= al1;
        }

#pragma unroll
        for (int kt = 0; kt < 4; kt++) {
            float p0 = S[2 * kt][0],     p1 = S[2 * kt][1];
            float p2 = S[2 * kt][2],     p3 = S[2 * kt][3];
            float p4 = S[2 * kt + 1][0], p5 = S[2 * kt + 1][1];
            float p6 = S[2 * kt + 1][2], p7 = S[2 * kt + 1][3];
            uint32_t ah[4], al[4];
            ah[0] = pack2(p0, p1); ah[1] = pack2(p2, p3);
            ah[2] = pack2(p4, p5); ah[3] = pack2(p6, p7);
            al[0] = pack2(lo_of(p0), lo_of(p1));
            al[1] = pack2(lo_of(p2), lo_of(p3));
            al[2] = pack2(lo_of(p4), lo_of(p5));
            al[3] = pack2(lo_of(p6), lo_of(p7));

            uint32_t voff = (uint32_t)(16 * kt + ((lane >> 3) & 1) * 8 + (lane & 7)) * FA_PITCH
                          + ((lane >> 4) * 8) * 2;
            uint32_t vh01[4], vh23[4], vl01[4], vl23[4];
            LDSM4T(vh01, kvb + FA_VH + voff);
            LDSM4T(vh23, kvb + FA_VH + voff + 32);
            LDSM4T(vl01, kvb + FA_VL + voff);
            LDSM4T(vl23, kvb + FA_VL + voff + 32);

            MMA16816(oc[0], ah, vh01[0], vh01[1]);
            MMA16816(oc[1], ah, vh01[2], vh01[3]);
            MMA16816(oc[2], ah, vh23[0], vh23[1]);
            MMA16816(oc[3], ah, vh23[2], vh23[3]);
            MMA16816(oc[0], al, vh01[0], vh01[1]);
            MMA16816(oc[1], al, vh01[2], vh01[3]);
            MMA16816(oc[2], al, vh23[0], vh23[1]);
            MMA16816(oc[3], al, vh23[2], vh23[3]);
            MMA16816(oc[0], ah, vl01[0], vl01[1]);
            MMA16816(oc[1], ah, vl01[2], vl01[3]);
            MMA16816(oc[2], ah, vl23[0], vl23[1]);
            MMA16816(oc[3], ah, vl23[2], vl23[3]);
        }

        cur = (cur == 2) ? 0 : cur + 1;
        nxt2 = (nxt2 == 2) ? 0 : nxt2 + 1;
    }

    float inv0 = 1.f / l_[0], inv1 = 1.f / l_[1];
    int row0 = rowbase + q0 + w * 16 + (lane >> 2);
    int row1 = row0 + 8;
#pragma unroll
    for (int j = 0; j < 4; j++) {
        float v[4] = {oc[j][0] * inv0, oc[j][1] * inv0,
                      oc[j][2] * inv1, oc[j][3] * inv1};
        if (do_gelu) {
#pragma unroll
            for (int i = 0; i < 4; i++) {
                float x = v[i];
                float cc = 0.7978845608028654f * (x + 0.044715f * x * x * x);
                v[i] = 0.5f * x * (1.f + tanhf(cc));
            }
        }
        __nv_bfloat16 h0, l0, h1, l1, h2, l2, h3, l3;
        split_bf(v[0], h0, l0); split_bf(v[1], h1, l1);
        split_bf(v[2], h2, l2); split_bf(v[3], h3, l3);
        int col = h * 32 + j * 8 + (lane & 3) * 2;
        __nv_bfloat162 ph0; ph0.x = h0; ph0.y = h1;
        __nv_bfloat162 pl0; pl0.x = l0; pl0.y = l1;
        __nv_bfloat162 ph1; ph1.x = h2; ph1.y = h3;
        __nv_bfloat162 pl1; pl1.x = l2; pl1.y = l3;
        *reinterpret_cast<uint32_t*>(outh + (size_t)row0 * Dc + col) =
            *reinterpret_cast<uint32_t*>(&ph0);
        *reinterpret_cast<uint32_t*>(outl + (size_t)row0 * Dc + col) =
            *reinterpret_cast<uint32_t*>(&pl0);
        *reinterpret_cast<uint32_t*>(outh + (size_t)row1 * Dc + col) =
            *reinterpret_cast<uint32_t*>(&ph1);
        *reinterpret_cast<uint32_t*>(outl + (size_t)row1 * Dc + col) =
            *reinterpret_cast<uint32_t*>(&pl1);
    }
}

// ---------------------------------------------------------------------------
// LayerNorm: warp per row, 8 rows/block
// ---------------------------------------------------------------------------
__global__ __launch_bounds__(256)
void ln_kernel(const float* __restrict__ x, const float* __restrict__ gg,
               const float* __restrict__ bb, float* __restrict__ out,
               __nv_bfloat16* __restrict__ ohi, __nv_bfloat16* __restrict__ olo)
{
    __shared__ float sg[Dc], sbb[Dc];
    int t = threadIdx.x;
    sg[t] = gg[t]; sbb[t] = bb[t];
    __syncthreads();

    int wid = t >> 5, lane = t & 31;
    int row = blockIdx.x * 8 + wid;

    float xv[8];
#pragma unroll
    for (int j = 0; j < 8; j++) xv[j] = x[(size_t)row * Dc + lane + 32 * j];
    float s = 0.f;
#pragma unroll
    for (int j = 0; j < 8; j++) s += xv[j];
#pragma unroll
    for (int o = 16; o >= 1; o >>= 1) s += __shfl_xor_sync(0xffffffffu, s, o);
    float mean = s * (1.f / 256.f);
    float vs = 0.f;
#pragma unroll
    for (int j = 0; j < 8; j++) { float d = xv[j] - mean; vs += d * d; }
#pragma unroll
    for (int o = 16; o >= 1; o >>= 1) vs += __shfl_xor_sync(0xffffffffu, vs, o);
    float rstd = rsqrtf(vs * (1.f / 256.f) + 1e-5f);

#pragma unroll
    for (int j = 0; j < 8; j++) {
        int col = lane + 32 * j;
        float r = (xv[j] - mean) * rstd * sg[col] + sbb[col];
        size_t o = (size_t)row * Dc + col;
        if (out) out[o] = r;
        if (ohi) {
            __nv_bfloat16 h, l;
            split_bf(r, h, l);
            ohi[o] = h;
            olo[o] = l;
        }
    }
}

// ---------------------------------------------------------------------------
// Fused ln2 + classifier: one block = 8 rows (warp per row).
// ---------------------------------------------------------------------------
__global__ __launch_bounds__(256)
void ln_cls_kernel(const float* __restrict__ x, const float* __restrict__ gg,
                   const float* __restrict__ bb, const float* __restrict__ Wc,
                   const float* __restrict__ bc, float* __restrict__ hout,
                   float* __restrict__ out)
{
    __shared__ float sW[Dc * Vc];
    __shared__ float sb2[Vc];
    __shared__ float sg[Dc], sbb[Dc];
    int t = threadIdx.x;
#pragma unroll
    for (int i = 0; i < 10; i++) {
        int idx = t + 256 * i;
        if (idx < Dc * Vc) sW[idx] = Wc[idx];
    }
    if (t < Vc) sb2[t] = bc[t];
    sg[t] = gg[t]; sbb[t] = bb[t];
    __syncthreads();

    int wid = t >> 5, lane = t & 31;
    int row = blockIdx.x * 8 + wid;

    float xv[8];
#pragma unroll
    for (int j = 0; j < 8; j++) xv[j] = x[(size_t)row * Dc + lane + 32 * j];
    float s = 0.f;
#pragma unroll
    for (int j = 0; j < 8; j++) s += xv[j];
#pragma unroll
    for (int o = 16; o >= 1; o >>= 1) s += __shfl_xor_sync(0xffffffffu, s, o);
    float mean = s * (1.f / 256.f);
    float vs = 0.f;
#pragma unroll
    for (int j = 0; j < 8; j++) { float d = xv[j] - mean; vs += d * d; }
#pragma unroll
    for (int o = 16; o >= 1; o >>= 1) vs += __shfl_xor_sync(0xffffffffu, vs, o);
    float rstd = rsqrtf(vs * (1.f / 256.f) + 1e-5f);

    float hv[8];
#pragma unroll
    for (int j = 0; j < 8; j++) {
        int col = lane + 32 * j;
        hv[j] = (xv[j] - mean) * rstd * sg[col] + sbb[col];
        hout[(size_t)row * Dc + col] = hv[j];
    }

    float sums[Vc];
#pragma unroll
    for (int v = 0; v < Vc; v++) {
        float p = 0.f;
#pragma unroll
        for (int j = 0; j < 8; j++) p += hv[j] * sW[(lane + 32 * j) * Vc + v];
#pragma unroll
        for (int o = 16; o >= 1; o >>= 1) p += __shfl_xor_sync(0xffffffffu, p, o);
        sums[v] = p;
    }
    if (lane == 0) {
#pragma unroll
        for (int v = 0; v < Vc; v++) out[(size_t)row * Vc + v] = sums[v] + sb2[v];
    }
}

// ---------------------------------------------------------------------------
// Host orchestration
// ---------------------------------------------------------------------------
extern "C" void kernel_launch(void* const* d_in, const int* in_sizes, int n_in,
                              void* d_out, int out_size)
{
    (void)in_sizes; (void)n_in; (void)out_size;

    const float* x     = (const float*)d_in[0];
    const int*   types = (const int*)  d_in[1];
    const int*   rel   = (const int*)  d_in[2];
    const float* W_in  = (const float*)d_in[3];
    const float* b_in  = (const float*)d_in[4];
    const float* Wq    = (const float*)d_in[5];
    const float* Wk    = (const float*)d_in[6];
    const float* Wv    = (const float*)d_in[7];
    const float* Wo    = (const float*)d_in[8];
    const float* bq    = (const float*)d_in[9];
    const float* bk    = (const float*)d_in[10];
    const float* bv    = (const float*)d_in[11];
    const float* bo    = (const float*)d_in[12];
    const float* relp  = (const float*)d_in[13];
    const float* Wqkv  = (const float*)d_in[14];
    const float* bqkv  = (const float*)d_in[15];
    const float* Wot   = (const float*)d_in[16];
    const float* bot   = (const float*)d_in[17];
    const float* ln1_g = (const float*)d_in[18];
    const float* ln1_b = (const float*)d_in[19];
    const float* ln2_g = (const float*)d_in[20];
    const float* ln2_b = (const float*)d_in[21];
    const float* Wf1   = (const float*)d_in[22];
    const float* bf1   = (const float*)d_in[23];
    const float* Wf2   = (const float*)d_in[24];
    const float* bf2   = (const float*)d_in[25];
    const float* Wc    = (const float*)d_in[26];
    const float* bc    = (const float*)d_in[27];
    float* out = (float*)d_out;

    float *qkvf, *tb, *bt;
    int *perm, *meta;
    cudaGetSymbolAddress((void**)&qkvf, g_qkv);
    cudaGetSymbolAddress((void**)&tb,   g_t);
    cudaGetSymbolAddress((void**)&bt,   g_bt);
    cudaGetSymbolAddress((void**)&perm, g_perm);
    cudaGetSymbolAddress((void**)&meta, g_meta);

    __nv_bfloat16 *xs, *hsA, *hsB, *msgs, *ffs, *lns;
    __nv_bfloat16 *binT, *qkvT, *woT, *encT, *wotT, *f1T, *f2T;
    cudaGetSymbolAddress((void**)&xs,   g_xs);
    cudaGetSymbolAddress((void**)&hsA,  g_hsA);
    cudaGetSymbolAddress((void**)&hsB,  g_hsB);
    cudaGetSymbolAddress((void**)&msgs, g_msgs);
    cudaGetSymbolAddress((void**)&ffs,  g_ffs);
    cudaGetSymbolAddress((void**)&lns,  g_lns);
    cudaGetSymbolAddress((void**)&binT, g_binT);
    cudaGetSymbolAddress((void**)&qkvT, g_qkvT);
    cudaGetSymbolAddress((void**)&woT,  g_woT);
    cudaGetSymbolAddress((void**)&encT, g_encT);
    cudaGetSymbolAddress((void**)&wotT, g_wotT);
    cudaGetSymbolAddress((void**)&f1T,  g_f1T);
    cudaGetSymbolAddress((void**)&f2T,  g_f2T);

    __nv_bfloat16* qkvH = (__nv_bfloat16*)qkvf;
    __nv_bfloat16* qkvL = qkvH + (size_t)Mc * QS;

    auto XH = xs;                 auto XL = xs + Mc * INc;
    auto HAH = hsA;               auto HAL = hsA + Mc * Dc;
    auto HBH = hsB;               auto HBL = hsB + Mc * Dc;
    auto MSH = msgs;              auto MSL = msgs + Mc * Dc;
    auto FFH = ffs;               auto FFL = ffs + (size_t)Mc * FFc;
    auto LNH = lns;               auto LNL = lns + Mc * Dc;
    auto BINH = binT;             auto BINL = binT + Dc * INc;
    auto ENCH = encT;             auto ENCL = encT + QS * Dc;
    auto WOTH = wotT;             auto WOTL = wotT + Dc * Dc;
    auto F1H = f1T;               auto F1L = f1T + FFc * Dc;
    auto F2H = f2T;               auto F2L = f2T + Dc * FFc;
    auto QT = [&](int l, int tp, int hl) {
        return qkvT + (((size_t)l * 2 + tp) * 2 + hl) * QS * Dc;
    };
    auto WT = [&](int l, int tp, int hl) {
        return woT + (((size_t)l * 2 + tp) * 2 + hl) * Dc * Dc;
    };

    cudaFuncSetAttribute(mm_bf, cudaFuncAttributeMaxDynamicSharedMemorySize, MMB_DYN);
    cudaFuncSetAttribute(attn3, cudaFuncAttributeMaxDynamicSharedMemorySize, FA_SMEM);

    const dim3 thr(256);
    const dim3 fagrid(Nc / 128, Hc, Bc);
    const int MT = Mc / 64;       // 256 m-tiles (untyped)
    const int MTP = MPAD / 64;    // 260 m-tiles (typed)

    // ---- build prep job table ----
    PrepJobs J{};
    int nj = 0, tiles = 0;
    auto add_job = [&](const float* src, __nv_bfloat16* dhi, __nv_bfloat16* dlo,
                       int K, int N, int trans) {
        J.src[nj] = src; J.dhi[nj] = dhi; J.dlo[nj] = dlo;
        J.K[nj] = K; J.N[nj] = N; J.trans[nj] = trans;
        J.tile_off[nj] = tiles;
        tiles += (N / 32) * (K / 32);
        nj++;
    };
    add_job(x,    XH,   XL,   Mc,  INc, 0);
    add_job(W_in, BINH, BINL, INc, Dc, 1);
    add_job(Wqkv, ENCH, ENCL, Dc, QS, 1);
    add_job(Wot,  WOTH, WOTL, Dc, Dc, 1);
    add_job(Wf1,  F1H,  F1L,  Dc, FFc, 1);
    add_job(Wf2,  F2H,  F2L,  FFc, Dc, 1);
    for (int l = 0; l < Lc; l++)
        for (int tp = 0; tp < 2; tp++) {
            const float* srcs[3] = {Wq, Wk, Wv};
            for (int s = 0; s < 3; s++)
                add_job(srcs[s] + ((size_t)l * 2 + tp) * Dc * Dc,
                        QT(l, tp, 0) + (size_t)s * Dc * Dc,
                        QT(l, tp, 1) + (size_t)s * Dc * Dc, Dc, Dc, 1);
            add_job(Wo + ((size_t)l * 2 + tp) * Dc * Dc,
                    WT(l, tp, 0), WT(l, tp, 1), Dc, Dc, 1);
        }
    J.tile_off[nj] = tiles;
    J.njobs = nj;

    // ---- launches ----
    setup_perm<<<1, Nc>>>(types, perm, meta);                                 // 0
    pack_b2<<<(Lc * 2 * QS + 255) / 256, thr>>>(bq, bk, bv, bt);              // 1
    prep_all<<<tiles, thr>>>(J);                                              // 2

    // input projection -> split h                                             // 3
    mm_bf<<<dim3(Dc / 128, MT), thr, MMB_DYN>>>(XH, XL, INc, Dc, BINH, BINL,
                                                nullptr, nullptr,
                                                b_in, nullptr, nullptr, nullptr,
                                                nullptr, nullptr, nullptr, HAH, HAL, 0);

    __nv_bfloat16 *hscH = HAH, *hscL = HAL, *hsnH = HBH, *hsnL = HBL;

    for (int l = 0; l < Lc; l++) {
        // typed QKV projection -> split bf16 qkv
        mm_bf<<<dim3(QS / 128, MTP), thr, MMB_DYN>>>(hscH, hscL, Dc, QS,
                                                     QT(l, 0, 0), QT(l, 0, 1),
                                                     QT(l, 1, 0), QT(l, 1, 1),
                                                     bt + (size_t)(l * 2) * QS,
                                                     bt + (size_t)(l * 2 + 1) * QS,
                                                     perm, meta, nullptr, nullptr,
                                                     nullptr, qkvH, qkvL, 0);

        attn3<<<fagrid, thr, FA_SMEM>>>(qkvH, qkvL, MSH, MSL,
                                        relp + (size_t)l * Rc * Hc, rel, 1);

        // typed output projection + split residual -> split h
        const float* bo0 = bo + (size_t)(l * 2 + 0) * Dc;
        const float* bo1 = bo + (size_t)(l * 2 + 1) * Dc;
        mm_bf<<<dim3(Dc / 128, MTP), thr, MMB_DYN>>>(MSH, MSL, Dc, Dc,
                                                     WT(l, 0, 0), WT(l, 0, 1),
                                                     WT(l, 1, 0), WT(l, 1, 1),
                                                     bo0, bo1, perm, meta,
                                                     hscH, hscL,
                                                     nullptr, hsnH, hsnL, 0);
        { auto th = hscH; hscH = hsnH; hsnH = th; }
        { auto tl = hscL; hscL = hsnL; hsnL = tl; }
    }

    // encoder
    mm_bf<<<dim3(QS / 128, MT), thr, MMB_DYN>>>(hscH, hscL, Dc, QS, ENCH, ENCL,
                                                nullptr, nullptr,
                                                bqkv, nullptr, nullptr, nullptr,
                                                nullptr, nullptr, nullptr, qkvH, qkvL, 0);

    attn3<<<fagrid, thr, FA_SMEM>>>(qkvH, qkvL, MSH, MSL, nullptr, nullptr, 0);

    // Wot + split residual -> tb fp32
    mm_bf<<<dim3(Dc / 128, MT), thr, MMB_DYN>>>(MSH, MSL, Dc, Dc, WOTH, WOTL,
                                                nullptr, nullptr,
                                                bot, nullptr, nullptr, nullptr,
                                                hscH, hscL, tb, nullptr, nullptr, 0);

    ln_kernel<<<Mc / 8, thr>>>(tb, ln1_g, ln1_b, nullptr, LNH, LNL);

    mm_bf<<<dim3(FFc / 128, MT), thr, MMB_DYN>>>(LNH, LNL, Dc, FFc, F1H, F1L,
                                                 nullptr, nullptr,
                                                 bf1, nullptr, nullptr, nullptr,
                                                 nullptr, nullptr, nullptr, FFH, FFL, 1);

    // FF2 + split residual (ln1 out) -> tb fp32
    mm_bf<<<dim3(Dc / 128, MT), thr, MMB_DYN>>>(FFH, FFL, FFc, Dc, F2H, F2L,
                                                nullptr, nullptr,
                                                bf2, nullptr, nullptr, nullptr,
                                                LNH, LNL, tb, nullptr, nullptr, 0);

    // fused ln2 + classifier: h -> out[Mc*Vc ...], logits -> out[0 ...]
    float* hfin = out + (size_t)Mc * Vc;
    ln_cls_kernel<<<Mc / 8, thr>>>(tb, ln2_g, ln2_b, Wc, bc, hfin, out);
}

// round 16
// speedup vs baseline: 1.5069x; 1.5069x over previous
#include <cuda_runtime.h>
#include <cuda_bf16.h>
#include <cstdint>
#include <math.h>

// Problem constants
constexpr int Bc  = 32;
constexpr int Nc  = 512;
constexpr int INc = 128;
constexpr int Dc  = 256;
constexpr int Hc  = 8;
constexpr int Lc  = 2;
constexpr int Rc  = 10;
constexpr int FFc = 2048;
constexpr int Vc  = 10;
constexpr int Mc  = Bc * Nc;        // 16384
constexpr int MPAD = Mc + 256;      // 16640 = 260*64
constexpr int QS  = 3 * Dc;         // 768

// -------- scratch (device globals) ----------
__device__ float g_qkv[Mc * QS];    // reused as 2x bf16 (hi|lo) qkv
__device__ float g_t[Mc * Dc];
__device__ float g_bt[Lc * 2 * QS];
__device__ int   g_perm[MPAD];
__device__ int   g_meta[4];
// bf16 hi/lo activation splits
__device__ __nv_bfloat16 g_xs[2][Mc * INc];
__device__ __nv_bfloat16 g_hsA[2][Mc * Dc];
__device__ __nv_bfloat16 g_hsB[2][Mc * Dc];
__device__ __nv_bfloat16 g_msgs[2][Mc * Dc];
__device__ __nv_bfloat16 g_ffs[2][(size_t)Mc * FFc];
__device__ __nv_bfloat16 g_lns[2][Mc * Dc];
// bf16 hi/lo transposed weights [N][K]
__device__ __nv_bfloat16 g_binT[2][Dc * INc];
__device__ __nv_bfloat16 g_qkvT[Lc][2][2][QS * Dc];   // [layer][type][hi/lo]
__device__ __nv_bfloat16 g_woT[Lc][2][2][Dc * Dc];
__device__ __nv_bfloat16 g_encT[2][QS * Dc];
__device__ __nv_bfloat16 g_wotT[2][Dc * Dc];
__device__ __nv_bfloat16 g_f1T[2][FFc * Dc];
__device__ __nv_bfloat16 g_f2T[2][Dc * FFc];

// ---------------------------------------------------------------------------
// helpers
// ---------------------------------------------------------------------------
__device__ __forceinline__ uint32_t smem_u32(const void* p) {
    uint32_t a;
    asm("{ .reg .u64 t; cvta.to.shared.u64 t, %1; cvt.u32.u64 %0, t; }"
        : "=r"(a) : "l"(p));
    return a;
}
#define SWZ128(o) ((o) ^ (((o) >> 3) & 0x70))

#define CP_A16(sm, gm) \
    asm volatile("cp.async.cg.shared.global [%0], [%1], 16;" :: "r"(sm), "l"(gm))
#define CP_COMMIT() asm volatile("cp.async.commit_group;" ::: "memory")
#define CP_WAIT1()  asm volatile("cp.async.wait_group 1;" ::: "memory")
#define CP_WAIT0()  asm volatile("cp.async.wait_group 0;" ::: "memory")

#define LDSM4(r, addr) \
    asm volatile("ldmatrix.sync.aligned.m8n8.x4.shared.b16 {%0,%1,%2,%3}, [%4];" \
        : "=r"((r)[0]), "=r"((r)[1]), "=r"((r)[2]), "=r"((r)[3]) : "r"(addr))
#define LDSM4T(r, addr) \
    asm volatile("ldmatrix.sync.aligned.m8n8.x4.trans.shared.b16 {%0,%1,%2,%3}, [%4];" \
        : "=r"((r)[0]), "=r"((r)[1]), "=r"((r)[2]), "=r"((r)[3]) : "r"(addr))

#define MMA16816(d, a, b0_, b1_) \
    asm volatile("mma.sync.aligned.m16n8k16.row.col.f32.bf16.bf16.f32 " \
        "{%0,%1,%2,%3}, {%4,%5,%6,%7}, {%8,%9}, {%0,%1,%2,%3};" \
        : "+f"((d)[0]), "+f"((d)[1]), "+f"((d)[2]), "+f"((d)[3]) \
        : "r"((a)[0]), "r"((a)[1]), "r"((a)[2]), "r"((a)[3]), "r"(b0_), "r"(b1_))

__device__ __forceinline__ void split_bf(float v, __nv_bfloat16& h, __nv_bfloat16& l) {
    h = __float2bfloat16(v);
    l = __float2bfloat16(v - __bfloat162float(h));
}
__device__ __forceinline__ uint32_t pack2(float lo, float hi) {
    uint32_t d;
    asm("cvt.rn.bf16x2.f32 %0, %1, %2;" : "=r"(d) : "f"(hi), "f"(lo));
    return d;
}
__device__ __forceinline__ float lo_of(float p) {
    return p - __bfloat162float(__float2bfloat16(p));
}

// ---------------------------------------------------------------------------
// setup_perm: partition rows by node type
// ---------------------------------------------------------------------------
__global__ void setup_perm(const int* __restrict__ types,
                           int* __restrict__ perm, int* __restrict__ meta)
{
    __shared__ int s[Nc];
    int n = threadIdx.x;
    int tp = types[n];
    s[n] = (tp == 0) ? 1 : 0;
    __syncthreads();
    for (int off = 1; off < Nc; off <<= 1) {
        int v = s[n];
        int add = (n >= off) ? s[n - off] : 0;
        __syncthreads();
        s[n] = v + add;
        __syncthreads();
    }
    int count0 = s[Nc - 1];
    int rank = (tp == 0) ? (s[n] - 1) : (n - s[n]);
    int rows0  = count0 * Bc;
    int rows0p = (rows0 + 127) & ~127;
    int base = (tp == 0) ? rank * Bc : rows0p + rank * Bc;
    for (int b = 0; b < Bc; b++)
        perm[base + b] = b * Nc + n;
    if (n == 0) meta[0] = rows0p;
    __syncthreads();
    int rows1 = (Nc - count0) * Bc;
    int total = rows0p + rows1;
    for (int i = n; i < MPAD; i += Nc)
        if ((i >= rows0 && i < rows0p) || i >= total) perm[i] = -1;
}

// ---------------------------------------------------------------------------
// prep_all: fused transpose(or copy)+bf16-split for all fp32->bf16 conversions
// ---------------------------------------------------------------------------
constexpr int MAXJOBS = 24;
struct PrepJobs {
    const float* src[MAXJOBS];
    __nv_bfloat16* dhi[MAXJOBS];
    __nv_bfloat16* dlo[MAXJOBS];
    int K[MAXJOBS];
    int N[MAXJOBS];
    int trans[MAXJOBS];
    int tile_off[MAXJOBS + 1];
    int njobs;
};

__global__ __launch_bounds__(256)
void prep_all(PrepJobs J)
{
    __shared__ float tile[32][33];
    int bid = blockIdx.x;
    int j = 0;
#pragma unroll 1
    while (j + 1 < J.njobs && bid >= J.tile_off[j + 1]) j++;
    int local = bid - J.tile_off[j];
    const float* src = J.src[j];
    __nv_bfloat16* dhi = J.dhi[j];
    __nv_bfloat16* dlo = J.dlo[j];
    int K = J.K[j], N = J.N[j];
    int tn = N >> 5;
    int n0 = (local % tn) * 32, k0 = (local / tn) * 32;

    int tx = threadIdx.x & 31, ty = threadIdx.x >> 5;
    if (J.trans[j]) {
#pragma unroll
        for (int i = 0; i < 4; i++)
            tile[ty + 8 * i][tx] = src[(size_t)(k0 + ty + 8 * i) * N + n0 + tx];
        __syncthreads();
#pragma unroll
        for (int i = 0; i < 4; i++) {
            int n = n0 + ty + 8 * i;
            int k = k0 + tx;
            float v = tile[tx][ty + 8 * i];
            __nv_bfloat16 h, l;
            split_bf(v, h, l);
            dhi[(size_t)n * K + k] = h;
            dlo[(size_t)n * K + k] = l;
        }
    } else {
#pragma unroll
        for (int i = 0; i < 4; i++) {
            size_t o = (size_t)(k0 + ty + 8 * i) * N + n0 + tx;
            float v = src[o];
            __nv_bfloat16 h, l;
            split_bf(v, h, l);
            dhi[o] = h;
            dlo[o] = l;
        }
    }
}

// pack typed QKV biases for all layers: out[Lc][2][QS]
__global__ void pack_b2(const float* __restrict__ bq, const float* __restrict__ bk,
                        const float* __restrict__ bv, float* __restrict__ out)
{
    int idx = blockIdx.x * 256 + threadIdx.x;
    if (idx >= Lc * 2 * QS) return;
    int lt = idx / QS, j = idx % QS;
    const float* src = (j < Dc) ? bq : ((j < 2 * Dc) ? bk : bv);
    out[idx] = src[lt * Dc + (j & (Dc - 1))];
}

// ---------------------------------------------------------------------------
// bf16 mma.sync GEMM with FUSED 3-product split (R14 winner): per 64-K chunk
// load Ahi,Alo,Bhi,Blo once, issue 24 MMA / 8 LDSM. Tile 64x128, warp tile
// 32x32, 2-stage cp.async, 2 CTAs/SM. Smem-bounce epilogue (coalesced 128B
// stores — R15 showed direct scattered STG loses badly).
// ---------------------------------------------------------------------------
constexpr int MM_A_HI = 0;
constexpr int MM_A_LO = 8192;
constexpr int MM_B_HI = 16384;
constexpr int MM_B_LO = 32768;
constexpr int MM_STAGE = 49152;       // Ahi 8K + Alo 8K + Bhi 16K + Blo 16K
constexpr int MMB_DYN = 2 * MM_STAGE; // 98304 >= bounce 33280

__global__ __launch_bounds__(256, 2)
void mm_bf(const __nv_bfloat16* __restrict__ Ahi, const __nv_bfloat16* __restrict__ Alo,
           int K, int N,
           const __nv_bfloat16* __restrict__ Bhi0, const __nv_bfloat16* __restrict__ Blo0,
           const __nv_bfloat16* __restrict__ Bhi1, const __nv_bfloat16* __restrict__ Blo1,
           const float* __restrict__ bias0, const float* __restrict__ bias1,
           const int* __restrict__ perm, const int* __restrict__ meta,
           const __nv_bfloat16* __restrict__ resH, const __nv_bfloat16* __restrict__ resL,
           float* __restrict__ Cf,
           __nv_bfloat16* __restrict__ Chi, __nv_bfloat16* __restrict__ Clo,
           int do_relu)
{
    extern __shared__ char sb[];
    __shared__ int sPerm[64];

    const int t = threadIdx.x;
    const int m0 = blockIdx.y * 64, n0 = blockIdx.x * 128;
    const bool typed = (perm != nullptr);

    const __nv_bfloat16* Bhi = Bhi0;
    const __nv_bfloat16* Blo = Blo0;
    const float* bias = bias0;
    if (typed && m0 >= meta[0]) { Bhi = Bhi1; Blo = Blo1; bias = bias1; }

    if (t < 64) sPerm[t] = typed ? perm[m0 + t] : (m0 + t);
    __syncthreads();

    // loader: lr = row lane (0..31), ch = 16B chunk (0..7)
    const int lr = t >> 3, ch = t & 7;
    int ag0 = sPerm[lr];      if (ag0 < 0) ag0 = 0;
    int ag1 = sPerm[lr + 32]; if (ag1 < 0) ag1 = 0;
    const uint32_t aoff0 = (uint32_t)ag0 * K + ch * 8;
    const uint32_t aoff1 = (uint32_t)ag1 * K + ch * 8;
    uint32_t boff[4], offB[4];
#pragma unroll
    for (int j = 0; j < 4; j++) {
        boff[j] = (uint32_t)(n0 + lr + 32 * j) * K + ch * 8;
        offB[j] = SWZ128((uint32_t)((lr + 32 * j) * 128 + ch * 16));
    }
    const uint32_t offA0 = SWZ128((uint32_t)(lr * 128 + ch * 16));
    const uint32_t offA1 = SWZ128((uint32_t)((lr + 32) * 128 + ch * 16));
    const uint32_t sbase = smem_u32(sb);
    const int S = K >> 6;              // K/64 chunks

    auto issue_load = [&](int kc, int stg) {
        int k0 = kc * 64;
        uint32_t so = sbase + stg * MM_STAGE;
        CP_A16(so + MM_A_HI + offA0, Ahi + aoff0 + k0);
        CP_A16(so + MM_A_HI + offA1, Ahi + aoff1 + k0);
        CP_A16(so + MM_A_LO + offA0, Alo + aoff0 + k0);
        CP_A16(so + MM_A_LO + offA1, Alo + aoff1 + k0);
#pragma unroll
        for (int j = 0; j < 4; j++) {
            CP_A16(so + MM_B_HI + offB[j], Bhi + boff[j] + k0);
            CP_A16(so + MM_B_LO + offB[j], Blo + boff[j] + k0);
        }
        CP_COMMIT();
    };

    float acc[2][4][4] = {};
    const int wid = t >> 5, lane = t & 31;
    const int wm = wid & 1, wn = wid >> 1;

    issue_load(0, 0);
    if (S > 1) issue_load(1, 1);

    for (int kc = 0; kc < S; kc++) {
        if (kc + 1 < S) { CP_WAIT1(); } else { CP_WAIT0(); }
        __syncthreads();
        uint32_t stg = sbase + (kc & 1) * MM_STAGE;
#pragma unroll
        for (int kk = 0; kk < 64; kk += 16) {
            uint32_t ah[2][4], al[2][4], bh[2][4], bl[2][4];
#pragma unroll
            for (int mi = 0; mi < 2; mi++) {
                int row = wm * 32 + mi * 16 + (lane & 15);
                int kcol = kk + ((lane >> 4) << 3);
                uint32_t off = SWZ128((uint32_t)(row * 128 + kcol * 2));
                LDSM4(ah[mi], stg + MM_A_HI + off);
                LDSM4(al[mi], stg + MM_A_LO + off);
            }
#pragma unroll
            for (int bj = 0; bj < 2; bj++) {
                int nrow = wn * 32 + bj * 16 + ((lane >> 4) & 1) * 8 + (lane & 7);
                int kcol = kk + ((lane >> 3) & 1) * 8;
                uint32_t off = SWZ128((uint32_t)(nrow * 128 + kcol * 2));
                LDSM4(bh[bj], stg + MM_B_HI + off);
                LDSM4(bl[bj], stg + MM_B_LO + off);
            }
#pragma unroll
            for (int mi = 0; mi < 2; mi++)
#pragma unroll
                for (int bj = 0; bj < 2; bj++) {
                    MMA16816(acc[mi][bj * 2],     ah[mi], bh[bj][0], bh[bj][1]);
                    MMA16816(acc[mi][bj * 2 + 1], ah[mi], bh[bj][2], bh[bj][3]);
                    MMA16816(acc[mi][bj * 2],     al[mi], bh[bj][0], bh[bj][1]);
                    MMA16816(acc[mi][bj * 2 + 1], al[mi], bh[bj][2], bh[bj][3]);
                    MMA16816(acc[mi][bj * 2],     ah[mi], bl[bj][0], bl[bj][1]);
                    MMA16816(acc[mi][bj * 2 + 1], ah[mi], bl[bj][2], bl[bj][3]);
                }
        }
        __syncthreads();
        if (kc + 2 < S) issue_load(kc + 2, kc & 1);
    }

    // bounce accumulators to smem (64 x 130 f32) for coalesced stores
    float* Cs = (float*)sb;
#pragma unroll
    for (int mi = 0; mi < 2; mi++)
#pragma unroll
        for (int nj = 0; nj < 4; nj++) {
            int row = wm * 32 + mi * 16 + (lane >> 2);
            int col = wn * 32 + nj * 8 + (lane & 3) * 2;
            *reinterpret_cast<float2*>(&Cs[row * 130 + col]) =
                make_float2(acc[mi][nj][0], acc[mi][nj][1]);
            *reinterpret_cast<float2*>(&Cs[(row + 8) * 130 + col]) =
                make_float2(acc[mi][nj][2], acc[mi][nj][3]);
        }
    __syncthreads();

    // vectorized write-out: thread = col pair x row group of 16
    {
        int cp2 = (t & 63) * 2, rg = t >> 6;
        float2 bv = *reinterpret_cast<const float2*>(&bias[n0 + cp2]);
        for (int i = 0; i < 16; i++) {
            int r = rg * 16 + i;
            int g = sPerm[r];
            if (g < 0) continue;
            float2 v = *reinterpret_cast<const float2*>(&Cs[r * 130 + cp2]);
            v.x += bv.x; v.y += bv.y;
            if (do_relu) { v.x = fmaxf(v.x, 0.f); v.y = fmaxf(v.y, 0.f); }
            size_t o = (size_t)g * N + n0 + cp2;
            if (resH) {
                __nv_bfloat162 rh = *reinterpret_cast<const __nv_bfloat162*>(resH + o);
                __nv_bfloat162 rl = *reinterpret_cast<const __nv_bfloat162*>(resL + o);
                v.x += __bfloat162float(rh.x) + __bfloat162float(rl.x);
                v.y += __bfloat162float(rh.y) + __bfloat162float(rl.y);
            }
            if (Cf) {
                *reinterpret_cast<float2*>(Cf + o) = v;
            }
            if (Chi) {
                __nv_bfloat16 h0, l0, h1, l1;
                split_bf(v.x, h0, l0); split_bf(v.y, h1, l1);
                __nv_bfloat162 ph; ph.x = h0; ph.y = h1;
                __nv_bfloat162 pl; pl.x = l0; pl.y = l1;
                *reinterpret_cast<__nv_bfloat162*>(Chi + o) = ph;
                *reinterpret_cast<__nv_bfloat162*>(Clo + o) = pl;
            }
        }
    }
}

// ---------------------------------------------------------------------------
// attn3: flash attention on tensor cores (R10 configuration: 3 KV bufs,
// launch_bounds(256,2), 84KB smem).
// ---------------------------------------------------------------------------
constexpr int FA_PITCH = 80;
constexpr int FA_Q_H = 0;
constexpr int FA_Q_L = 10240;
constexpr int FA_KV  = 20480;            // + buf*20480 (3 bufs)
constexpr int FA_KH = 0, FA_KL = 5120, FA_VH = 10240, FA_VL = 15360;
constexpr int FA_BIAS = FA_KV + 3 * 20480;   // 81920
constexpr int FA_SMEM = FA_BIAS + Nc * 4;    // 83968

__global__ __launch_bounds__(256, 2)
void attn3(const __nv_bfloat16* __restrict__ qh, const __nv_bfloat16* __restrict__ ql,
           __nv_bfloat16* __restrict__ outh, __nv_bfloat16* __restrict__ outl,
           const float* __restrict__ relp, const int* __restrict__ rel_ids,
           int do_gelu)
{
    extern __shared__ char sm[];
    const uint32_t sb = smem_u32(sm);
    const int t = threadIdx.x, lane = t & 31, w = t >> 5;
    const int h = blockIdx.y, b = blockIdx.z;
    const int rowbase = b * Nc;
    const int q0 = blockIdx.x * 128;

    float* sBias = (float*)(sm + FA_BIAS);
    for (int i = t; i < Nc; i += 256)
        sBias[i] = relp ? relp[rel_ids[rowbase + i] * Hc + h] : 0.f;

#pragma unroll
    for (int i = 0; i < 2; i++) {
        int id = t + 256 * i;
        int r = id >> 2, ch = id & 3;
        size_t go = (size_t)(rowbase + q0 + r) * QS + h * 32 + ch * 8;
        CP_A16(sb + FA_Q_H + r * FA_PITCH + ch * 16, qh + go);
        CP_A16(sb + FA_Q_L + r * FA_PITCH + ch * 16, ql + go);
    }
    CP_COMMIT();

    auto load_kv = [&](int c, int buf) {
        uint32_t base = sb + FA_KV + buf * 20480;
        int kr0 = rowbase + c * 64;
        int r = t >> 2, ch = t & 3;
#pragma unroll
        for (int m = 0; m < 4; m++) {
            const __nv_bfloat16* src = (m & 1) ? ql : qh;
            int coloff = ((m >> 1) ? 2 * Dc : Dc) + h * 32;
            uint32_t dst = base + ((m >> 1) ? ((m & 1) ? FA_VL : FA_VH)
                                            : ((m & 1) ? FA_KL : FA_KH));
            CP_A16(dst + r * FA_PITCH + ch * 16,
                   src + (size_t)(kr0 + r) * QS + coloff + ch * 8);
        }
        CP_COMMIT();
    };

    uint32_t qfh[2][4], qfl[2][4];
    float m_[2] = {-1e30f, -1e30f};
    float l_[2] = {0.f, 0.f};
    float oc[4][4] = {};

    load_kv(0, 0);
    load_kv(1, 1);

    constexpr int NCH = Nc / 64;   // 8
    int cur = 0, nxt2 = 2;
    for (int c = 0; c < NCH; c++) {
        if (c + 1 < NCH) { CP_WAIT1(); } else { CP_WAIT0(); }
        __syncthreads();
        if (c + 2 < NCH) load_kv(c + 2, nxt2);
        if (c == 0) {
#pragma unroll
            for (int ks = 0; ks < 2; ks++) {
                uint32_t off = (uint32_t)(w * 16 + (lane & 15)) * FA_PITCH
                             + (ks * 16 + (lane >> 4) * 8) * 2;
                LDSM4(qfh[ks], sb + FA_Q_H + off);
                LDSM4(qfl[ks], sb + FA_Q_L + off);
            }
        }
        uint32_t kvb = sb + FA_KV + cur * 20480;

        float S[8][4];
#pragma unroll
        for (int j = 0; j < 8; j++) { S[j][0] = S[j][1] = S[j][2] = S[j][3] = 0.f; }
#pragma unroll
        for (int pj = 0; pj < 4; pj++) {
#pragma unroll
            for (int ks = 0; ks < 2; ks++) {
                uint32_t off = (uint32_t)(pj * 16 + ((lane >> 4) & 1) * 8 + (lane & 7)) * FA_PITCH
                             + (ks * 16 + ((lane >> 3) & 1) * 8) * 2;
                uint32_t kh[4], kl[4];
                LDSM4(kh, kvb + FA_KH + off);
                LDSM4(kl, kvb + FA_KL + off);
                MMA16816(S[2 * pj],     qfh[ks], kh[0], kh[1]);
                MMA16816(S[2 * pj + 1], qfh[ks], kh[2], kh[3]);
                MMA16816(S[2 * pj],     qfl[ks], kh[0], kh[1]);
                MMA16816(S[2 * pj + 1], qfl[ks], kh[2], kh[3]);
                MMA16816(S[2 * pj],     qfh[ks], kl[0], kl[1]);
                MMA16816(S[2 * pj + 1], qfh[ks], kl[2], kl[3]);
            }
        }

        const float scl = 0.17677669529663687f;
        float mc0 = -1e30f, mc1 = -1e30f;
#pragma unroll
        for (int j = 0; j < 8; j++) {
            float b0 = sBias[c * 64 + j * 8 + (lane & 3) * 2];
            float b1 = sBias[c * 64 + j * 8 + (lane & 3) * 2 + 1];
            S[j][0] = fmaf(S[j][0], scl, b0);
            S[j][1] = fmaf(S[j][1], scl, b1);
            S[j][2] = fmaf(S[j][2], scl, b0);
            S[j][3] = fmaf(S[j][3], scl, b1);
            mc0 = fmaxf(mc0, fmaxf(S[j][0], S[j][1]));
            mc1 = fmaxf(mc1, fmaxf(S[j][2], S[j][3]));
        }
#pragma unroll
        for (int o = 1; o <= 2; o <<= 1) {
            mc0 = fmaxf(mc0, __shfl_xor_sync(0xffffffffu, mc0, o));
            mc1 = fmaxf(mc1, __shfl_xor_sync(0xffffffffu, mc1, o));
        }
        float mn0 = fmaxf(m_[0], mc0), mn1 = fmaxf(m_[1], mc1);
        float al0 = __expf(m_[0] - mn0), al1 = __expf(m_[1] - mn1);
        m_[0] = mn0; m_[1] = mn1;
        float ps0 = 0.f, ps1 = 0.f;
#pragma unroll
        for (int j = 0; j < 8; j++) {
            S[j][0] = __expf(S[j][0] - mn0);
            S[j][1] = __expf(S[j][1] - mn0);
            S[j][2] = __expf(S[j][2] - mn1);
            S[j][3] = __expf(S[j][3] - mn1);
            ps0 += S[j][0] + S[j][1];
            ps1 += S[j][2] + S[j][3];
        }
#pragma unroll
        for (int o = 1; o <= 2; o <<= 1) {
            ps0 += __shfl_xor_sync(0xffffffffu, ps0, o);
            ps1 += __shfl_xor_sync(0xffffffffu, ps1, o);
        }
        l_[0] = l_[0] * al0 + ps0;
        l_[1] = l_[1] * al1 + ps1;
#pragma unroll
        for (int j = 0; j < 4; j++) {
            oc[j][0] *= al0; oc[j][1] *= al0;
            oc[j][2] *= al1; oc[j][3] *= al1;
        }

#pragma unroll
        for (int kt = 0; kt < 4; kt++) {
            float p0 = S[2 * kt][0],     p1 = S[2 * kt][1];
            float p2 = S[2 * kt][2],     p3 = S[2 * kt][3];
            float p4 = S[2 * kt + 1][0], p5 = S[2 * kt + 1][1];
            float p6 = S[2 * kt + 1][2], p7 = S[2 * kt + 1][3];
            uint32_t ah[4], al[4];
            ah[0] = pack2(p0, p1); ah[1] = pack2(p2, p3);
            ah[2] = pack2(p4, p5); ah[3] = pack2(p6, p7);
            al[0] = pack2(lo_of(p0), lo_of(p1));
            al[1] = pack2(lo_of(p2), lo_of(p3));
            al[2] = pack2(lo_of(p4), lo_of(p5));
            al[3] = pack2(lo_of(p6), lo_of(p7));

            uint32_t voff = (uint32_t)(16 * kt + ((lane >> 3) & 1) * 8 + (lane & 7)) * FA_PITCH
                          + ((lane >> 4) * 8) * 2;
            uint32_t vh01[4], vh23[4], vl01[4], vl23[4];
            LDSM4T(vh01, kvb + FA_VH + voff);
            LDSM4T(vh23, kvb + FA_VH + voff + 32);
            LDSM4T(vl01, kvb + FA_VL + voff);
            LDSM4T(vl23, kvb + FA_VL + voff + 32);

            MMA16816(oc[0], ah, vh01[0], vh01[1]);
            MMA16816(oc[1], ah, vh01[2], vh01[3]);
            MMA16816(oc[2], ah, vh23[0], vh23[1]);
            MMA16816(oc[3], ah, vh23[2], vh23[3]);
            MMA16816(oc[0], al, vh01[0], vh01[1]);
            MMA16816(oc[1], al, vh01[2], vh01[3]);
            MMA16816(oc[2], al, vh23[0], vh23[1]);
            MMA16816(oc[3], al, vh23[2], vh23[3]);
            MMA16816(oc[0], ah, vl01[0], vl01[1]);
            MMA16816(oc[1], ah, vl01[2], vl01[3]);
            MMA16816(oc[2], ah, vl23[0], vl23[1]);
            MMA16816(oc[3], ah, vl23[2], vl23[3]);
        }

        cur = (cur == 2) ? 0 : cur + 1;
        nxt2 = (nxt2 == 2) ? 0 : nxt2 + 1;
    }

    float inv0 = 1.f / l_[0], inv1 = 1.f / l_[1];
    int row0 = rowbase + q0 + w * 16 + (lane >> 2);
    int row1 = row0 + 8;
#pragma unroll
    for (int j = 0; j < 4; j++) {
        float v[4] = {oc[j][0] * inv0, oc[j][1] * inv0,
                      oc[j][2] * inv1, oc[j][3] * inv1};
        if (do_gelu) {
#pragma unroll
            for (int i = 0; i < 4; i++) {
                float x = v[i];
                float cc = 0.7978845608028654f * (x + 0.044715f * x * x * x);
                v[i] = 0.5f * x * (1.f + tanhf(cc));
            }
        }
        __nv_bfloat16 h0, l0, h1, l1, h2, l2, h3, l3;
        split_bf(v[0], h0, l0); split_bf(v[1], h1, l1);
        split_bf(v[2], h2, l2); split_bf(v[3], h3, l3);
        int col = h * 32 + j * 8 + (lane & 3) * 2;
        __nv_bfloat162 ph0; ph0.x = h0; ph0.y = h1;
        __nv_bfloat162 pl0; pl0.x = l0; pl0.y = l1;
        __nv_bfloat162 ph1; ph1.x = h2; ph1.y = h3;
        __nv_bfloat162 pl1; pl1.x = l2; pl1.y = l3;
        *reinterpret_cast<uint32_t*>(outh + (size_t)row0 * Dc + col) =
            *reinterpret_cast<uint32_t*>(&ph0);
        *reinterpret_cast<uint32_t*>(outl + (size_t)row0 * Dc + col) =
            *reinterpret_cast<uint32_t*>(&pl0);
        *reinterpret_cast<uint32_t*>(outh + (size_t)row1 * Dc + col) =
            *reinterpret_cast<uint32_t*>(&ph1);
        *reinterpret_cast<uint32_t*>(outl + (size_t)row1 * Dc + col) =
            *reinterpret_cast<uint32_t*>(&pl1);
    }
}

// ---------------------------------------------------------------------------
// LayerNorm: warp per row, 8 rows/block
// ---------------------------------------------------------------------------
__global__ __launch_bounds__(256)
void ln_kernel(const float* __restrict__ x, const float* __restrict__ gg,
               const float* __restrict__ bb, float* __restrict__ out,
               __nv_bfloat16* __restrict__ ohi, __nv_bfloat16* __restrict__ olo)
{
    __shared__ float sg[Dc], sbb[Dc];
    int t = threadIdx.x;
    sg[t] = gg[t]; sbb[t] = bb[t];
    __syncthreads();

    int wid = t >> 5, lane = t & 31;
    int row = blockIdx.x * 8 + wid;

    float xv[8];
#pragma unroll
    for (int j = 0; j < 8; j++) xv[j] = x[(size_t)row * Dc + lane + 32 * j];
    float s = 0.f;
#pragma unroll
    for (int j = 0; j < 8; j++) s += xv[j];
#pragma unroll
    for (int o = 16; o >= 1; o >>= 1) s += __shfl_xor_sync(0xffffffffu, s, o);
    float mean = s * (1.f / 256.f);
    float vs = 0.f;
#pragma unroll
    for (int j = 0; j < 8; j++) { float d = xv[j] - mean; vs += d * d; }
#pragma unroll
    for (int o = 16; o >= 1; o >>= 1) vs += __shfl_xor_sync(0xffffffffu, vs, o);
    float rstd = rsqrtf(vs * (1.f / 256.f) + 1e-5f);

#pragma unroll
    for (int j = 0; j < 8; j++) {
        int col = lane + 32 * j;
        float r = (xv[j] - mean) * rstd * sg[col] + sbb[col];
        size_t o = (size_t)row * Dc + col;
        if (out) out[o] = r;
        if (ohi) {
            __nv_bfloat16 h, l;
            split_bf(r, h, l);
            ohi[o] = h;
            olo[o] = l;
        }
    }
}

// ---------------------------------------------------------------------------
// Fused ln2 + classifier: one block = 8 rows (warp per row).
// ---------------------------------------------------------------------------
__global__ __launch_bounds__(256)
void ln_cls_kernel(const float* __restrict__ x, const float* __restrict__ gg,
                   const float* __restrict__ bb, const float* __restrict__ Wc,
                   const float* __restrict__ bc, float* __restrict__ hout,
                   float* __restrict__ out)
{
    __shared__ float sW[Dc * Vc];
    __shared__ float sb2[Vc];
    __shared__ float sg[Dc], sbb[Dc];
    int t = threadIdx.x;
#pragma unroll
    for (int i = 0; i < 10; i++) {
        int idx = t + 256 * i;
        if (idx < Dc * Vc) sW[idx] = Wc[idx];
    }
    if (t < Vc) sb2[t] = bc[t];
    sg[t] = gg[t]; sbb[t] = bb[t];
    __syncthreads();

    int wid = t >> 5, lane = t & 31;
    int row = blockIdx.x * 8 + wid;

    float xv[8];
#pragma unroll
    for (int j = 0; j < 8; j++) xv[j] = x[(size_t)row * Dc + lane + 32 * j];
    float s = 0.f;
#pragma unroll
    for (int j = 0; j < 8; j++) s += xv[j];
#pragma unroll
    for (int o = 16; o >= 1; o >>= 1) s += __shfl_xor_sync(0xffffffffu, s, o);
    float mean = s * (1.f / 256.f);
    float vs = 0.f;
#pragma unroll
    for (int j = 0; j < 8; j++) { float d = xv[j] - mean; vs += d * d; }
#pragma unroll
    for (int o = 16; o >= 1; o >>= 1) vs += __shfl_xor_sync(0xffffffffu, vs, o);
    float rstd = rsqrtf(vs * (1.f / 256.f) + 1e-5f);

    float hv[8];
#pragma unroll
    for (int j = 0; j < 8; j++) {
        int col = lane + 32 * j;
        hv[j] = (xv[j] - mean) * rstd * sg[col] + sbb[col];
        hout[(size_t)row * Dc + col] = hv[j];
    }

    float sums[Vc];
#pragma unroll
    for (int v = 0; v < Vc; v++) {
        float p = 0.f;
#pragma unroll
        for (int j = 0; j < 8; j++) p += hv[j] * sW[(lane + 32 * j) * Vc + v];
#pragma unroll
        for (int o = 16; o >= 1; o >>= 1) p += __shfl_xor_sync(0xffffffffu, p, o);
        sums[v] = p;
    }
    if (lane == 0) {
#pragma unroll
        for (int v = 0; v < Vc; v++) out[(size_t)row * Vc + v] = sums[v] + sb2[v];
    }
}

// ---------------------------------------------------------------------------
// Host orchestration
// ---------------------------------------------------------------------------
extern "C" void kernel_launch(void* const* d_in, const int* in_sizes, int n_in,
                              void* d_out, int out_size)
{
    (void)in_sizes; (void)n_in; (void)out_size;

    const float* x     = (const float*)d_in[0];
    const int*   types = (const int*)  d_in[1];
    const int*   rel   = (const int*)  d_in[2];
    const float* W_in  = (const float*)d_in[3];
    const float* b_in  = (const float*)d_in[4];
    const float* Wq    = (const float*)d_in[5];
    const float* Wk    = (const float*)d_in[6];
    const float* Wv    = (const float*)d_in[7];
    const float* Wo    = (const float*)d_in[8];
    const float* bq    = (const float*)d_in[9];
    const float* bk    = (const float*)d_in[10];
    const float* bv    = (const float*)d_in[11];
    const float* bo    = (const float*)d_in[12];
    const float* relp  = (const float*)d_in[13];
    const float* Wqkv  = (const float*)d_in[14];
    const float* bqkv  = (const float*)d_in[15];
    const float* Wot   = (const float*)d_in[16];
    const float* bot   = (const float*)d_in[17];
    const float* ln1_g = (const float*)d_in[18];
    const float* ln1_b = (const float*)d_in[19];
    const float* ln2_g = (const float*)d_in[20];
    const float* ln2_b = (const float*)d_in[21];
    const float* Wf1   = (const float*)d_in[22];
    const float* bf1   = (const float*)d_in[23];
    const float* Wf2   = (const float*)d_in[24];
    const float* bf2   = (const float*)d_in[25];
    const float* Wc    = (const float*)d_in[26];
    const float* bc    = (const float*)d_in[27];
    float* out = (float*)d_out;

    float *qkvf, *tb, *bt;
    int *perm, *meta;
    cudaGetSymbolAddress((void**)&qkvf, g_qkv);
    cudaGetSymbolAddress((void**)&tb,   g_t);
    cudaGetSymbolAddress((void**)&bt,   g_bt);
    cudaGetSymbolAddress((void**)&perm, g_perm);
    cudaGetSymbolAddress((void**)&meta, g_meta);

    __nv_bfloat16 *xs, *hsA, *hsB, *msgs, *ffs, *lns;
    __nv_bfloat16 *binT, *qkvT, *woT, *encT, *wotT, *f1T, *f2T;
    cudaGetSymbolAddress((void**)&xs,   g_xs);
    cudaGetSymbolAddress((void**)&hsA,  g_hsA);
    cudaGetSymbolAddress((void**)&hsB,  g_hsB);
    cudaGetSymbolAddress((void**)&msgs, g_msgs);
    cudaGetSymbolAddress((void**)&ffs,  g_ffs);
    cudaGetSymbolAddress((void**)&lns,  g_lns);
    cudaGetSymbolAddress((void**)&binT, g_binT);
    cudaGetSymbolAddress((void**)&qkvT, g_qkvT);
    cudaGetSymbolAddress((void**)&woT,  g_woT);
    cudaGetSymbolAddress((void**)&encT, g_encT);
    cudaGetSymbolAddress((void**)&wotT, g_wotT);
    cudaGetSymbolAddress((void**)&f1T,  g_f1T);
    cudaGetSymbolAddress((void**)&f2T,  g_f2T);

    __nv_bfloat16* qkvH = (__nv_bfloat16*)qkvf;
    __nv_bfloat16* qkvL = qkvH + (size_t)Mc * QS;

    auto XH = xs;                 auto XL = xs + Mc * INc;
    auto HAH = hsA;               auto HAL = hsA + Mc * Dc;
    auto HBH = hsB;               auto HBL = hsB + Mc * Dc;
    auto MSH = msgs;              auto MSL = msgs + Mc * Dc;
    auto FFH = ffs;               auto FFL = ffs + (size_t)Mc * FFc;
    auto LNH = lns;               auto LNL = lns + Mc * Dc;
    auto BINH = binT;             auto BINL = binT + Dc * INc;
    auto ENCH = encT;             auto ENCL = encT + QS * Dc;
    auto WOTH = wotT;             auto WOTL = wotT + Dc * Dc;
    auto F1H = f1T;               auto F1L = f1T + FFc * Dc;
    auto F2H = f2T;               auto F2L = f2T + Dc * FFc;
    auto QT = [&](int l, int tp, int hl) {
        return qkvT + (((size_t)l * 2 + tp) * 2 + hl) * QS * Dc;
    };
    auto WT = [&](int l, int tp, int hl) {
        return woT + (((size_t)l * 2 + tp) * 2 + hl) * Dc * Dc;
    };

    cudaFuncSetAttribute(mm_bf, cudaFuncAttributeMaxDynamicSharedMemorySize, MMB_DYN);
    cudaFuncSetAttribute(attn3, cudaFuncAttributeMaxDynamicSharedMemorySize, FA_SMEM);

    const dim3 thr(256);
    const dim3 fagrid(Nc / 128, Hc, Bc);
    const int MT = Mc / 64;       // 256 m-tiles (untyped)
    const int MTP = MPAD / 64;    // 260 m-tiles (typed)

    // ---- build prep job table ----
    PrepJobs J{};
    int nj = 0, tiles = 0;
    auto add_job = [&](const float* src, __nv_bfloat16* dhi, __nv_bfloat16* dlo,
                       int K, int N, int trans) {
        J.src[nj] = src; J.dhi[nj] = dhi; J.dlo[nj] = dlo;
        J.K[nj] = K; J.N[nj] = N; J.trans[nj] = trans;
        J.tile_off[nj] = tiles;
        tiles += (N / 32) * (K / 32);
        nj++;
    };
    add_job(x,    XH,   XL,   Mc,  INc, 0);
    add_job(W_in, BINH, BINL, INc, Dc, 1);
    add_job(Wqkv, ENCH, ENCL, Dc, QS, 1);
    add_job(Wot,  WOTH, WOTL, Dc, Dc, 1);
    add_job(Wf1,  F1H,  F1L,  Dc, FFc, 1);
    add_job(Wf2,  F2H,  F2L,  FFc, Dc, 1);
    for (int l = 0; l < Lc; l++)
        for (int tp = 0; tp < 2; tp++) {
            const float* srcs[3] = {Wq, Wk, Wv};
            for (int s = 0; s < 3; s++)
                add_job(srcs[s] + ((size_t)l * 2 + tp) * Dc * Dc,
                        QT(l, tp, 0) + (size_t)s * Dc * Dc,
                        QT(l, tp, 1) + (size_t)s * Dc * Dc, Dc, Dc, 1);
            add_job(Wo + ((size_t)l * 2 + tp) * Dc * Dc,
                    WT(l, tp, 0), WT(l, tp, 1), Dc, Dc, 1);
        }
    J.tile_off[nj] = tiles;
    J.njobs = nj;

    // ---- launches ----
    setup_perm<<<1, Nc>>>(types, perm, meta);                                 // 0
    pack_b2<<<(Lc * 2 * QS + 255) / 256, thr>>>(bq, bk, bv, bt);              // 1
    prep_all<<<tiles, thr>>>(J);                                              // 2

    // input projection -> split h                                             // 3
    mm_bf<<<dim3(Dc / 128, MT), thr, MMB_DYN>>>(XH, XL, INc, Dc, BINH, BINL,
                                                nullptr, nullptr,
                                                b_in, nullptr, nullptr, nullptr,
                                                nullptr, nullptr, nullptr, HAH, HAL, 0);

    __nv_bfloat16 *hscH = HAH, *hscL = HAL, *hsnH = HBH, *hsnL = HBL;

    for (int l = 0; l < Lc; l++) {
        // typed QKV projection -> split bf16 qkv
        mm_bf<<<dim3(QS / 128, MTP), thr, MMB_DYN>>>(hscH, hscL, Dc, QS,
                                                     QT(l, 0, 0), QT(l, 0, 1),
                                                     QT(l, 1, 0), QT(l, 1, 1),
                                                     bt + (size_t)(l * 2) * QS,
                                                     bt + (size_t)(l * 2 + 1) * QS,
                                                     perm, meta, nullptr, nullptr,
                                                     nullptr, qkvH, qkvL, 0);

        attn3<<<fagrid, thr, FA_SMEM>>>(qkvH, qkvL, MSH, MSL,
                                        relp + (size_t)l * Rc * Hc, rel, 1);

        // typed output projection + split residual -> split h
        const float* bo0 = bo + (size_t)(l * 2 + 0) * Dc;
        const float* bo1 = bo + (size_t)(l * 2 + 1) * Dc;
        mm_bf<<<dim3(Dc / 128, MTP), thr, MMB_DYN>>>(MSH, MSL, Dc, Dc,
                                                     WT(l, 0, 0), WT(l, 0, 1),
                                                     WT(l, 1, 0), WT(l, 1, 1),
                                                     bo0, bo1, perm, meta,
                                                     hscH, hscL,
                                                     nullptr, hsnH, hsnL, 0);
        { auto th = hscH; hscH = hsnH; hsnH = th; }
        { auto tl = hscL; hscL = hsnL; hsnL = tl; }
    }

    // encoder
    mm_bf<<<dim3(QS / 128, MT), thr, MMB_DYN>>>(hscH, hscL, Dc, QS, ENCH, ENCL,
                                                nullptr, nullptr,
                                                bqkv, nullptr, nullptr, nullptr,
                                                nullptr, nullptr, nullptr, qkvH, qkvL, 0);

    attn3<<<fagrid, thr, FA_SMEM>>>(qkvH, qkvL, MSH, MSL, nullptr, nullptr, 0);

    // Wot + split residual -> tb fp32
    mm_bf<<<dim3(Dc / 128, MT), thr, MMB_DYN>>>(MSH, MSL, Dc, Dc, WOTH, WOTL,
                                                nullptr, nullptr,
                                                bot, nullptr, nullptr, nullptr,
                                                hscH, hscL, tb, nullptr, nullptr, 0);

    ln_kernel<<<Mc / 8, thr>>>(tb, ln1_g, ln1_b, nullptr, LNH, LNL);

    mm_bf<<<dim3(FFc / 128, MT), thr, MMB_DYN>>>(LNH, LNL, Dc, FFc, F1H, F1L,
                                                 nullptr, nullptr,
                                                 bf1, nullptr, nullptr, nullptr,
                                                 nullptr, nullptr, nullptr, FFH, FFL, 1);

    // FF2 + split residual (ln1 out) -> tb fp32
    mm_bf<<<dim3(Dc / 128, MT), thr, MMB_DYN>>>(FFH, FFL, FFc, Dc, F2H, F2L,
                                                nullptr, nullptr,
                                                bf2, nullptr, nullptr, nullptr,
                                                LNH, LNL, tb, nullptr, nullptr, 0);

    // fused ln2 + classifier: h -> out[Mc*Vc ...], logits -> out[0 ...]
    float* hfin = out + (size_t)Mc * Vc;
    ln_cls_kernel<<<Mc / 8, thr>>>(tb, ln2_g, ln2_b, Wc, bc, hfin, out);
}